// round 11
// baseline (speedup 1.0000x reference)
#include <cuda_runtime.h>
#include <cstdint>

// Problem shape (fixed): B=2, S=2048, D=1024, H=2048, E=8, k=2
#define T_TOK 4096   // B*S tokens
#define DIM   1024   // D
#define HID   2048   // H
#define NEXP  8      // E

// ---------------- static device scratch (no runtime allocation) -------------
__device__ int   g_cnt[NEXP];                       // tokens per expert
__device__ int   g_tok[NEXP * T_TOK];               // token*2 + slot
__device__ float g_score[NEXP * T_TOK];             // softmax score of that slot
__device__ float g_h[(size_t)NEXP * T_TOK * HID];   // hidden activations (per expert segment)
__device__ float g_eo[(size_t)T_TOK * 2 * DIM];     // per-(token,slot) expert output

// ---------------------------------------------------------------------------
__global__ void zero_cnt_kernel() {
    if (threadIdx.x < NEXP) g_cnt[threadIdx.x] = 0;
}

// One block (128 threads) per token: logits = x @ Wr + br, top-2, softmax,
// append to per-expert lists.
__global__ void router_kernel(const float* __restrict__ x,
                              const float* __restrict__ Wr,
                              const float* __restrict__ br) {
    const int t   = blockIdx.x;
    const int tid = threadIdx.x;

    float acc[NEXP];
#pragma unroll
    for (int e = 0; e < NEXP; e++) acc[e] = 0.f;

    const float4* Wr4 = reinterpret_cast<const float4*>(Wr);   // [D][E] rows of 8 floats
    const float*  xr  = x + (size_t)t * DIM;

#pragma unroll
    for (int it = 0; it < DIM / 128; it++) {
        int d = it * 128 + tid;
        float xv  = xr[d];
        float4 w0 = Wr4[d * 2];
        float4 w1 = Wr4[d * 2 + 1];
        acc[0] = fmaf(xv, w0.x, acc[0]); acc[1] = fmaf(xv, w0.y, acc[1]);
        acc[2] = fmaf(xv, w0.z, acc[2]); acc[3] = fmaf(xv, w0.w, acc[3]);
        acc[4] = fmaf(xv, w1.x, acc[4]); acc[5] = fmaf(xv, w1.y, acc[5]);
        acc[6] = fmaf(xv, w1.z, acc[6]); acc[7] = fmaf(xv, w1.w, acc[7]);
    }

    // warp reduce
#pragma unroll
    for (int o = 16; o > 0; o >>= 1) {
#pragma unroll
        for (int e = 0; e < NEXP; e++)
            acc[e] += __shfl_down_sync(0xffffffffu, acc[e], o);
    }

    __shared__ float sred[4][NEXP];
    const int wid  = tid >> 5;
    const int lane = tid & 31;
    if (lane == 0) {
#pragma unroll
        for (int e = 0; e < NEXP; e++) sred[wid][e] = acc[e];
    }
    __syncthreads();

    if (tid == 0) {
        float lg[NEXP];
#pragma unroll
        for (int e = 0; e < NEXP; e++)
            lg[e] = sred[0][e] + sred[1][e] + sred[2][e] + sred[3][e] + br[e];

        // top-2 (strict > keeps lowest index on ties, matching jax top_k)
        int i0 = 0;
#pragma unroll
        for (int e = 1; e < NEXP; e++) if (lg[e] > lg[i0]) i0 = e;
        int i1 = (i0 == 0) ? 1 : 0;
#pragma unroll
        for (int e = 0; e < NEXP; e++)
            if (e != i0 && lg[e] > lg[i1]) i1 = e;

        float ev  = expf(lg[i1] - lg[i0]);     // <= 1
        float inv = 1.f / (1.f + ev);
        float p0  = inv;
        float p1  = ev * inv;

        int pos0 = atomicAdd(&g_cnt[i0], 1);
        g_tok[i0 * T_TOK + pos0]   = t * 2;
        g_score[i0 * T_TOK + pos0] = p0;
        int pos1 = atomicAdd(&g_cnt[i1], 1);
        g_tok[i1 * T_TOK + pos1]   = t * 2 + 1;
        g_score[i1 * T_TOK + pos1] = p1;
    }
}

// ---------------------------------------------------------------------------
// GEMM1: for expert e, h[e*T + pos, :] = relu( x[tok(pos), :] @ W1[e] + b1[e] )
// Tile 128x128, BK=16, 256 threads, 8x8 micro-tile.
__global__ __launch_bounds__(256, 2)
void gemm1_kernel(const float* __restrict__ x,
                  const float* __restrict__ W1,
                  const float* __restrict__ b1) {
    const int e   = blockIdx.z;
    const int cnt = g_cnt[e];
    const int m0  = blockIdx.y * 128;
    if (m0 >= cnt) return;
    const int n0  = blockIdx.x * 128;

    __shared__ float  As[16][128];
    __shared__ float4 Bs[16][32];

    const int tid = threadIdx.x;
    const int tx  = tid & 15;
    const int ty  = tid >> 4;

    // A loading assignment: 512 float4 per K-tile, 2 per thread
    const int arow = tid >> 2;   // 0..63, second is +64
    const int akq  = tid & 3;    // float4 index along K within tile
    int tokA[2];
#pragma unroll
    for (int p = 0; p < 2; p++) {
        int pos = m0 + arow + p * 64;
        int tk  = 0;
        if (pos < cnt) tk = g_tok[e * T_TOK + pos] >> 1;   // token id
        tokA[p] = tk;
    }
    const float4* x4 = reinterpret_cast<const float4*>(x);

    // B loading assignment
    const int bn4 = tid & 31;
    const int bk  = tid >> 5;    // 0..7, +8 for p=1
    const float4* W4 = reinterpret_cast<const float4*>(W1);
    const size_t  wbase = (size_t)e * DIM * (HID / 4);

    float acc[8][8];
#pragma unroll
    for (int i = 0; i < 8; i++)
#pragma unroll
        for (int j = 0; j < 8; j++) acc[i][j] = 0.f;

    for (int k0 = 0; k0 < DIM; k0 += 16) {
#pragma unroll
        for (int p = 0; p < 2; p++) {
            float4 v = x4[(size_t)tokA[p] * (DIM / 4) + (k0 >> 2) + akq];
            int r = arow + p * 64;
            As[akq * 4 + 0][r] = v.x;
            As[akq * 4 + 1][r] = v.y;
            As[akq * 4 + 2][r] = v.z;
            As[akq * 4 + 3][r] = v.w;
        }
#pragma unroll
        for (int p = 0; p < 2; p++) {
            int k = k0 + bk + p * 8;
            Bs[bk + p * 8][bn4] = W4[wbase + (size_t)k * (HID / 4) + (n0 >> 2) + bn4];
        }
        __syncthreads();

#pragma unroll
        for (int kk = 0; kk < 16; kk++) {
            const float4* Ar = reinterpret_cast<const float4*>(&As[kk][0]);
            float4 a0 = Ar[ty * 2];
            float4 a1 = Ar[ty * 2 + 1];
            float4 b0 = Bs[kk][tx * 2];
            float4 b1v = Bs[kk][tx * 2 + 1];
            float av[8] = {a0.x, a0.y, a0.z, a0.w, a1.x, a1.y, a1.z, a1.w};
            float bv[8] = {b0.x, b0.y, b0.z, b0.w, b1v.x, b1v.y, b1v.z, b1v.w};
#pragma unroll
            for (int i = 0; i < 8; i++)
#pragma unroll
                for (int j = 0; j < 8; j++)
                    acc[i][j] = fmaf(av[i], bv[j], acc[i][j]);
        }
        __syncthreads();
    }

    // epilogue: + b1, relu, store to g_h
    const float4* b14 = reinterpret_cast<const float4*>(b1);
    float4 bb0 = b14[(e * HID + n0) / 4 + tx * 2];
    float4 bb1 = b14[(e * HID + n0) / 4 + tx * 2 + 1];
    float4* h4 = reinterpret_cast<float4*>(g_h);
#pragma unroll
    for (int i = 0; i < 8; i++) {
        int pos = m0 + ty * 8 + i;
        if (pos < cnt) {
            size_t base = ((size_t)e * T_TOK + pos) * (HID / 4) + (n0 >> 2) + tx * 2;
            float4 o0, o1;
            o0.x = fmaxf(acc[i][0] + bb0.x, 0.f);
            o0.y = fmaxf(acc[i][1] + bb0.y, 0.f);
            o0.z = fmaxf(acc[i][2] + bb0.z, 0.f);
            o0.w = fmaxf(acc[i][3] + bb0.w, 0.f);
            o1.x = fmaxf(acc[i][4] + bb1.x, 0.f);
            o1.y = fmaxf(acc[i][5] + bb1.y, 0.f);
            o1.z = fmaxf(acc[i][6] + bb1.z, 0.f);
            o1.w = fmaxf(acc[i][7] + bb1.w, 0.f);
            h4[base]     = o0;
            h4[base + 1] = o1;
        }
    }
}

// ---------------------------------------------------------------------------
// GEMM2: eo[tok2, :] = score * ( h[e*T+pos, :] @ W2[e] + b2[e] )
__global__ __launch_bounds__(256, 2)
void gemm2_kernel(const float* __restrict__ W2,
                  const float* __restrict__ b2) {
    const int e   = blockIdx.z;
    const int cnt = g_cnt[e];
    const int m0  = blockIdx.y * 128;
    if (m0 >= cnt) return;
    const int n0  = blockIdx.x * 128;   // over DIM

    __shared__ float  As[16][128];
    __shared__ float4 Bs[16][32];

    const int tid = threadIdx.x;
    const int tx  = tid & 15;
    const int ty  = tid >> 4;

    const int arow = tid >> 2;
    const int akq  = tid & 3;
    const int bn4  = tid & 31;
    const int bk   = tid >> 5;

    const float4* h4  = reinterpret_cast<const float4*>(g_h);
    const float4* W4  = reinterpret_cast<const float4*>(W2);
    const size_t  abase = ((size_t)e * T_TOK + m0) * (HID / 4);
    const size_t  wbase = (size_t)e * HID * (DIM / 4);

    float acc[8][8];
#pragma unroll
    for (int i = 0; i < 8; i++)
#pragma unroll
        for (int j = 0; j < 8; j++) acc[i][j] = 0.f;

    for (int k0 = 0; k0 < HID; k0 += 16) {
#pragma unroll
        for (int p = 0; p < 2; p++) {
            int r = arow + p * 64;
            // rows >= cnt read stale-but-finite scratch; stores are masked below
            float4 v = h4[abase + (size_t)r * (HID / 4) + (k0 >> 2) + akq];
            As[akq * 4 + 0][r] = v.x;
            As[akq * 4 + 1][r] = v.y;
            As[akq * 4 + 2][r] = v.z;
            As[akq * 4 + 3][r] = v.w;
        }
#pragma unroll
        for (int p = 0; p < 2; p++) {
            int k = k0 + bk + p * 8;
            Bs[bk + p * 8][bn4] = W4[wbase + (size_t)k * (DIM / 4) + (n0 >> 2) + bn4];
        }
        __syncthreads();

#pragma unroll
        for (int kk = 0; kk < 16; kk++) {
            const float4* Ar = reinterpret_cast<const float4*>(&As[kk][0]);
            float4 a0 = Ar[ty * 2];
            float4 a1 = Ar[ty * 2 + 1];
            float4 b0 = Bs[kk][tx * 2];
            float4 b1v = Bs[kk][tx * 2 + 1];
            float av[8] = {a0.x, a0.y, a0.z, a0.w, a1.x, a1.y, a1.z, a1.w};
            float bv[8] = {b0.x, b0.y, b0.z, b0.w, b1v.x, b1v.y, b1v.z, b1v.w};
#pragma unroll
            for (int i = 0; i < 8; i++)
#pragma unroll
                for (int j = 0; j < 8; j++)
                    acc[i][j] = fmaf(av[i], bv[j], acc[i][j]);
        }
        __syncthreads();
    }

    const float4* b24 = reinterpret_cast<const float4*>(b2);
    float4 bb0 = b24[(e * DIM + n0) / 4 + tx * 2];
    float4 bb1 = b24[(e * DIM + n0) / 4 + tx * 2 + 1];
    float4* eo4 = reinterpret_cast<float4*>(g_eo);
#pragma unroll
    for (int i = 0; i < 8; i++) {
        int pos = m0 + ty * 8 + i;
        if (pos < cnt) {
            int   entry = g_tok[e * T_TOK + pos];      // token*2 + slot
            float sc    = g_score[e * T_TOK + pos];
            size_t base = (size_t)entry * (DIM / 4) + (n0 >> 2) + tx * 2;
            float4 o0, o1;
            o0.x = (acc[i][0] + bb0.x) * sc;
            o0.y = (acc[i][1] + bb0.y) * sc;
            o0.z = (acc[i][2] + bb0.z) * sc;
            o0.w = (acc[i][3] + bb0.w) * sc;
            o1.x = (acc[i][4] + bb1.x) * sc;
            o1.y = (acc[i][5] + bb1.y) * sc;
            o1.z = (acc[i][6] + bb1.z) * sc;
            o1.w = (acc[i][7] + bb1.w) * sc;
            eo4[base]     = o0;
            eo4[base + 1] = o1;
        }
    }
}

// ---------------------------------------------------------------------------
// out[t, :] = eo[2t, :] + eo[2t+1, :]
__global__ void combine_kernel(float* __restrict__ out) {
    int i  = blockIdx.x * 256 + threadIdx.x;  // over T*D/4
    int t  = i >> 8;                          // D/4 = 256 float4 per row
    int d4 = i & 255;
    const float4* eo4 = reinterpret_cast<const float4*>(g_eo);
    float4 u = eo4[(size_t)(t * 2) * (DIM / 4) + d4];
    float4 v = eo4[(size_t)(t * 2 + 1) * (DIM / 4) + d4];
    float4 r;
    r.x = u.x + v.x; r.y = u.y + v.y; r.z = u.z + v.z; r.w = u.w + v.w;
    reinterpret_cast<float4*>(out)[i] = r;
}

// ---------------------------------------------------------------------------
extern "C" void kernel_launch(void* const* d_in, const int* in_sizes, int n_in,
                              void* d_out, int out_size) {
    (void)in_sizes; (void)n_in; (void)out_size;
    const float* x  = (const float*)d_in[0];
    const float* Wr = (const float*)d_in[1];
    const float* br = (const float*)d_in[2];
    const float* W1 = (const float*)d_in[3];
    const float* b1 = (const float*)d_in[4];
    const float* W2 = (const float*)d_in[5];
    const float* b2 = (const float*)d_in[6];
    // d_in[7] is k (==2), hardcoded

    zero_cnt_kernel<<<1, 32>>>();
    router_kernel<<<T_TOK, 128>>>(x, Wr, br);

    dim3 g1(HID / 128, T_TOK / 128, NEXP);   // early-exit past per-expert count
    gemm1_kernel<<<g1, 256>>>(x, W1, b1);

    dim3 g2(DIM / 128, T_TOK / 128, NEXP);
    gemm2_kernel<<<g2, 256>>>(W2, b2);

    combine_kernel<<<(T_TOK * DIM / 4) / 256, 256>>>((float*)d_out);
}

// round 12
// speedup vs baseline: 1.0008x; 1.0008x over previous
#include <cuda_runtime.h>
#include <cstdint>

// Problem shape (fixed): B=2, S=2048, D=1024, H=2048, E=8, k=2
#define T_TOK 4096   // B*S tokens
#define DIM   1024   // D
#define HID   2048   // H
#define NEXP  8      // E

// ---------------- static device scratch (no runtime allocation) -------------
__device__ int   g_cnt[NEXP];                       // tokens per expert
__device__ int   g_tok[NEXP * T_TOK];               // token*2 + slot
__device__ float g_score[NEXP * T_TOK];             // softmax score of that slot
__device__ float g_h[(size_t)NEXP * T_TOK * HID];   // hidden activations (per expert segment)
__device__ float g_eo[(size_t)T_TOK * 2 * DIM];     // per-(token,slot) expert output

// ---------------------------------------------------------------------------
__global__ void zero_cnt_kernel() {
    if (threadIdx.x < NEXP) g_cnt[threadIdx.x] = 0;
}

// One block (128 threads) per token: logits = x @ Wr + br, top-2, softmax,
// append to per-expert lists.
__global__ void router_kernel(const float* __restrict__ x,
                              const float* __restrict__ Wr,
                              const float* __restrict__ br) {
    const int t   = blockIdx.x;
    const int tid = threadIdx.x;

    float acc[NEXP];
#pragma unroll
    for (int e = 0; e < NEXP; e++) acc[e] = 0.f;

    const float4* Wr4 = reinterpret_cast<const float4*>(Wr);   // [D][E] rows of 8 floats
    const float*  xr  = x + (size_t)t * DIM;

#pragma unroll
    for (int it = 0; it < DIM / 128; it++) {
        int d = it * 128 + tid;
        float xv  = xr[d];
        float4 w0 = Wr4[d * 2];
        float4 w1 = Wr4[d * 2 + 1];
        acc[0] = fmaf(xv, w0.x, acc[0]); acc[1] = fmaf(xv, w0.y, acc[1]);
        acc[2] = fmaf(xv, w0.z, acc[2]); acc[3] = fmaf(xv, w0.w, acc[3]);
        acc[4] = fmaf(xv, w1.x, acc[4]); acc[5] = fmaf(xv, w1.y, acc[5]);
        acc[6] = fmaf(xv, w1.z, acc[6]); acc[7] = fmaf(xv, w1.w, acc[7]);
    }

    // warp reduce
#pragma unroll
    for (int o = 16; o > 0; o >>= 1) {
#pragma unroll
        for (int e = 0; e < NEXP; e++)
            acc[e] += __shfl_down_sync(0xffffffffu, acc[e], o);
    }

    __shared__ float sred[4][NEXP];
    const int wid  = tid >> 5;
    const int lane = tid & 31;
    if (lane == 0) {
#pragma unroll
        for (int e = 0; e < NEXP; e++) sred[wid][e] = acc[e];
    }
    __syncthreads();

    if (tid == 0) {
        float lg[NEXP];
#pragma unroll
        for (int e = 0; e < NEXP; e++)
            lg[e] = sred[0][e] + sred[1][e] + sred[2][e] + sred[3][e] + br[e];

        // top-2 (strict > keeps lowest index on ties, matching jax top_k)
        int i0 = 0;
#pragma unroll
        for (int e = 1; e < NEXP; e++) if (lg[e] > lg[i0]) i0 = e;
        int i1 = (i0 == 0) ? 1 : 0;
#pragma unroll
        for (int e = 0; e < NEXP; e++)
            if (e != i0 && lg[e] > lg[i1]) i1 = e;

        float ev  = expf(lg[i1] - lg[i0]);     // <= 1
        float inv = 1.f / (1.f + ev);
        float p0  = inv;
        float p1  = ev * inv;

        int pos0 = atomicAdd(&g_cnt[i0], 1);
        g_tok[i0 * T_TOK + pos0]   = t * 2;
        g_score[i0 * T_TOK + pos0] = p0;
        int pos1 = atomicAdd(&g_cnt[i1], 1);
        g_tok[i1 * T_TOK + pos1]   = t * 2 + 1;
        g_score[i1 * T_TOK + pos1] = p1;
    }
}

// ---------------------------------------------------------------------------
// GEMM1: for expert e, h[e*T + pos, :] = relu( x[tok(pos), :] @ W1[e] + b1[e] )
// Tile 128x128, BK=16, 256 threads, 8x8 micro-tile.
__global__ __launch_bounds__(256, 2)
void gemm1_kernel(const float* __restrict__ x,
                  const float* __restrict__ W1,
                  const float* __restrict__ b1) {
    const int e   = blockIdx.z;
    const int cnt = g_cnt[e];
    const int m0  = blockIdx.y * 128;
    if (m0 >= cnt) return;
    const int n0  = blockIdx.x * 128;

    __shared__ float  As[16][128];
    __shared__ float4 Bs[16][32];

    const int tid = threadIdx.x;
    const int tx  = tid & 15;
    const int ty  = tid >> 4;

    // A loading assignment: 512 float4 per K-tile, 2 per thread
    const int arow = tid >> 2;   // 0..63, second is +64
    const int akq  = tid & 3;    // float4 index along K within tile
    int tokA[2];
#pragma unroll
    for (int p = 0; p < 2; p++) {
        int pos = m0 + arow + p * 64;
        int tk  = 0;
        if (pos < cnt) tk = g_tok[e * T_TOK + pos] >> 1;   // token id
        tokA[p] = tk;
    }
    const float4* x4 = reinterpret_cast<const float4*>(x);

    // B loading assignment
    const int bn4 = tid & 31;
    const int bk  = tid >> 5;    // 0..7, +8 for p=1
    const float4* W4 = reinterpret_cast<const float4*>(W1);
    const size_t  wbase = (size_t)e * DIM * (HID / 4);

    float acc[8][8];
#pragma unroll
    for (int i = 0; i < 8; i++)
#pragma unroll
        for (int j = 0; j < 8; j++) acc[i][j] = 0.f;

    for (int k0 = 0; k0 < DIM; k0 += 16) {
#pragma unroll
        for (int p = 0; p < 2; p++) {
            float4 v = x4[(size_t)tokA[p] * (DIM / 4) + (k0 >> 2) + akq];
            int r = arow + p * 64;
            As[akq * 4 + 0][r] = v.x;
            As[akq * 4 + 1][r] = v.y;
            As[akq * 4 + 2][r] = v.z;
            As[akq * 4 + 3][r] = v.w;
        }
#pragma unroll
        for (int p = 0; p < 2; p++) {
            int k = k0 + bk + p * 8;
            Bs[bk + p * 8][bn4] = W4[wbase + (size_t)k * (HID / 4) + (n0 >> 2) + bn4];
        }
        __syncthreads();

#pragma unroll
        for (int kk = 0; kk < 16; kk++) {
            const float4* Ar = reinterpret_cast<const float4*>(&As[kk][0]);
            float4 a0 = Ar[ty * 2];
            float4 a1 = Ar[ty * 2 + 1];
            float4 b0 = Bs[kk][tx * 2];
            float4 b1v = Bs[kk][tx * 2 + 1];
            float av[8] = {a0.x, a0.y, a0.z, a0.w, a1.x, a1.y, a1.z, a1.w};
            float bv[8] = {b0.x, b0.y, b0.z, b0.w, b1v.x, b1v.y, b1v.z, b1v.w};
#pragma unroll
            for (int i = 0; i < 8; i++)
#pragma unroll
                for (int j = 0; j < 8; j++)
                    acc[i][j] = fmaf(av[i], bv[j], acc[i][j]);
        }
        __syncthreads();
    }

    // epilogue: + b1, relu, store to g_h
    const float4* b14 = reinterpret_cast<const float4*>(b1);
    float4 bb0 = b14[(e * HID + n0) / 4 + tx * 2];
    float4 bb1 = b14[(e * HID + n0) / 4 + tx * 2 + 1];
    float4* h4 = reinterpret_cast<float4*>(g_h);
#pragma unroll
    for (int i = 0; i < 8; i++) {
        int pos = m0 + ty * 8 + i;
        if (pos < cnt) {
            size_t base = ((size_t)e * T_TOK + pos) * (HID / 4) + (n0 >> 2) + tx * 2;
            float4 o0, o1;
            o0.x = fmaxf(acc[i][0] + bb0.x, 0.f);
            o0.y = fmaxf(acc[i][1] + bb0.y, 0.f);
            o0.z = fmaxf(acc[i][2] + bb0.z, 0.f);
            o0.w = fmaxf(acc[i][3] + bb0.w, 0.f);
            o1.x = fmaxf(acc[i][4] + bb1.x, 0.f);
            o1.y = fmaxf(acc[i][5] + bb1.y, 0.f);
            o1.z = fmaxf(acc[i][6] + bb1.z, 0.f);
            o1.w = fmaxf(acc[i][7] + bb1.w, 0.f);
            h4[base]     = o0;
            h4[base + 1] = o1;
        }
    }
}

// ---------------------------------------------------------------------------
// GEMM2: eo[tok2, :] = score * ( h[e*T+pos, :] @ W2[e] + b2[e] )
__global__ __launch_bounds__(256, 2)
void gemm2_kernel(const float* __restrict__ W2,
                  const float* __restrict__ b2) {
    const int e   = blockIdx.z;
    const int cnt = g_cnt[e];
    const int m0  = blockIdx.y * 128;
    if (m0 >= cnt) return;
    const int n0  = blockIdx.x * 128;   // over DIM

    __shared__ float  As[16][128];
    __shared__ float4 Bs[16][32];

    const int tid = threadIdx.x;
    const int tx  = tid & 15;
    const int ty  = tid >> 4;

    const int arow = tid >> 2;
    const int akq  = tid & 3;
    const int bn4  = tid & 31;
    const int bk   = tid >> 5;

    const float4* h4  = reinterpret_cast<const float4*>(g_h);
    const float4* W4  = reinterpret_cast<const float4*>(W2);
    const size_t  abase = ((size_t)e * T_TOK + m0) * (HID / 4);
    const size_t  wbase = (size_t)e * HID * (DIM / 4);

    float acc[8][8];
#pragma unroll
    for (int i = 0; i < 8; i++)
#pragma unroll
        for (int j = 0; j < 8; j++) acc[i][j] = 0.f;

    for (int k0 = 0; k0 < HID; k0 += 16) {
#pragma unroll
        for (int p = 0; p < 2; p++) {
            int r = arow + p * 64;
            // rows >= cnt read stale-but-finite scratch; stores are masked below
            float4 v = h4[abase + (size_t)r * (HID / 4) + (k0 >> 2) + akq];
            As[akq * 4 + 0][r] = v.x;
            As[akq * 4 + 1][r] = v.y;
            As[akq * 4 + 2][r] = v.z;
            As[akq * 4 + 3][r] = v.w;
        }
#pragma unroll
        for (int p = 0; p < 2; p++) {
            int k = k0 + bk + p * 8;
            Bs[bk + p * 8][bn4] = W4[wbase + (size_t)k * (DIM / 4) + (n0 >> 2) + bn4];
        }
        __syncthreads();

#pragma unroll
        for (int kk = 0; kk < 16; kk++) {
            const float4* Ar = reinterpret_cast<const float4*>(&As[kk][0]);
            float4 a0 = Ar[ty * 2];
            float4 a1 = Ar[ty * 2 + 1];
            float4 b0 = Bs[kk][tx * 2];
            float4 b1v = Bs[kk][tx * 2 + 1];
            float av[8] = {a0.x, a0.y, a0.z, a0.w, a1.x, a1.y, a1.z, a1.w};
            float bv[8] = {b0.x, b0.y, b0.z, b0.w, b1v.x, b1v.y, b1v.z, b1v.w};
#pragma unroll
            for (int i = 0; i < 8; i++)
#pragma unroll
                for (int j = 0; j < 8; j++)
                    acc[i][j] = fmaf(av[i], bv[j], acc[i][j]);
        }
        __syncthreads();
    }

    const float4* b24 = reinterpret_cast<const float4*>(b2);
    float4 bb0 = b24[(e * DIM + n0) / 4 + tx * 2];
    float4 bb1 = b24[(e * DIM + n0) / 4 + tx * 2 + 1];
    float4* eo4 = reinterpret_cast<float4*>(g_eo);
#pragma unroll
    for (int i = 0; i < 8; i++) {
        int pos = m0 + ty * 8 + i;
        if (pos < cnt) {
            int   entry = g_tok[e * T_TOK + pos];      // token*2 + slot
            float sc    = g_score[e * T_TOK + pos];
            size_t base = (size_t)entry * (DIM / 4) + (n0 >> 2) + tx * 2;
            float4 o0, o1;
            o0.x = (acc[i][0] + bb0.x) * sc;
            o0.y = (acc[i][1] + bb0.y) * sc;
            o0.z = (acc[i][2] + bb0.z) * sc;
            o0.w = (acc[i][3] + bb0.w) * sc;
            o1.x = (acc[i][4] + bb1.x) * sc;
            o1.y = (acc[i][5] + bb1.y) * sc;
            o1.z = (acc[i][6] + bb1.z) * sc;
            o1.w = (acc[i][7] + bb1.w) * sc;
            eo4[base]     = o0;
            eo4[base + 1] = o1;
        }
    }
}

// ---------------------------------------------------------------------------
// out[t, :] = eo[2t, :] + eo[2t+1, :]
__global__ void combine_kernel(float* __restrict__ out) {
    int i  = blockIdx.x * 256 + threadIdx.x;  // over T*D/4
    int t  = i >> 8;                          // D/4 = 256 float4 per row
    int d4 = i & 255;
    const float4* eo4 = reinterpret_cast<const float4*>(g_eo);
    float4 u = eo4[(size_t)(t * 2) * (DIM / 4) + d4];
    float4 v = eo4[(size_t)(t * 2 + 1) * (DIM / 4) + d4];
    float4 r;
    r.x = u.x + v.x; r.y = u.y + v.y; r.z = u.z + v.z; r.w = u.w + v.w;
    reinterpret_cast<float4*>(out)[i] = r;
}

// ---------------------------------------------------------------------------
extern "C" void kernel_launch(void* const* d_in, const int* in_sizes, int n_in,
                              void* d_out, int out_size) {
    (void)in_sizes; (void)n_in; (void)out_size;
    const float* x  = (const float*)d_in[0];
    const float* Wr = (const float*)d_in[1];
    const float* br = (const float*)d_in[2];
    const float* W1 = (const float*)d_in[3];
    const float* b1 = (const float*)d_in[4];
    const float* W2 = (const float*)d_in[5];
    const float* b2 = (const float*)d_in[6];
    // d_in[7] is k (==2), hardcoded

    zero_cnt_kernel<<<1, 32>>>();
    router_kernel<<<T_TOK, 128>>>(x, Wr, br);

    dim3 g1(HID / 128, T_TOK / 128, NEXP);   // early-exit past per-expert count
    gemm1_kernel<<<g1, 256>>>(x, W1, b1);

    dim3 g2(DIM / 128, T_TOK / 128, NEXP);
    gemm2_kernel<<<g2, 256>>>(W2, b2);

    combine_kernel<<<(T_TOK * DIM / 4) / 256, 256>>>((float*)d_out);
}

// round 13
// speedup vs baseline: 1.0024x; 1.0015x over previous
#include <cuda_runtime.h>
#include <cstdint>

// Problem shape (fixed): B=2, S=2048, D=1024, H=2048, E=8, k=2
#define T_TOK 4096   // B*S tokens
#define DIM   1024   // D
#define HID   2048   // H
#define NEXP  8      // E

// ---------------- static device scratch (no runtime allocation) -------------
__device__ int   g_cnt[NEXP];                       // tokens per expert
__device__ int   g_tok[NEXP * T_TOK];               // token*2 + slot
__device__ float g_score[NEXP * T_TOK];             // softmax score of that slot
__device__ float g_h[(size_t)NEXP * T_TOK * HID];   // hidden activations (per expert segment)
__device__ float g_eo[(size_t)T_TOK * 2 * DIM];     // per-(token,slot) expert output

// ---------------------------------------------------------------------------
__global__ void zero_cnt_kernel() {
    if (threadIdx.x < NEXP) g_cnt[threadIdx.x] = 0;
}

// One block (128 threads) per token: logits = x @ Wr + br, top-2, softmax,
// append to per-expert lists.
__global__ void router_kernel(const float* __restrict__ x,
                              const float* __restrict__ Wr,
                              const float* __restrict__ br) {
    const int t   = blockIdx.x;
    const int tid = threadIdx.x;

    float acc[NEXP];
#pragma unroll
    for (int e = 0; e < NEXP; e++) acc[e] = 0.f;

    const float4* Wr4 = reinterpret_cast<const float4*>(Wr);   // [D][E] rows of 8 floats
    const float*  xr  = x + (size_t)t * DIM;

#pragma unroll
    for (int it = 0; it < DIM / 128; it++) {
        int d = it * 128 + tid;
        float xv  = xr[d];
        float4 w0 = Wr4[d * 2];
        float4 w1 = Wr4[d * 2 + 1];
        acc[0] = fmaf(xv, w0.x, acc[0]); acc[1] = fmaf(xv, w0.y, acc[1]);
        acc[2] = fmaf(xv, w0.z, acc[2]); acc[3] = fmaf(xv, w0.w, acc[3]);
        acc[4] = fmaf(xv, w1.x, acc[4]); acc[5] = fmaf(xv, w1.y, acc[5]);
        acc[6] = fmaf(xv, w1.z, acc[6]); acc[7] = fmaf(xv, w1.w, acc[7]);
    }

    // warp reduce
#pragma unroll
    for (int o = 16; o > 0; o >>= 1) {
#pragma unroll
        for (int e = 0; e < NEXP; e++)
            acc[e] += __shfl_down_sync(0xffffffffu, acc[e], o);
    }

    __shared__ float sred[4][NEXP];
    const int wid  = tid >> 5;
    const int lane = tid & 31;
    if (lane == 0) {
#pragma unroll
        for (int e = 0; e < NEXP; e++) sred[wid][e] = acc[e];
    }
    __syncthreads();

    if (tid == 0) {
        float lg[NEXP];
#pragma unroll
        for (int e = 0; e < NEXP; e++)
            lg[e] = sred[0][e] + sred[1][e] + sred[2][e] + sred[3][e] + br[e];

        // top-2 (strict > keeps lowest index on ties, matching jax top_k)
        int i0 = 0;
#pragma unroll
        for (int e = 1; e < NEXP; e++) if (lg[e] > lg[i0]) i0 = e;
        int i1 = (i0 == 0) ? 1 : 0;
#pragma unroll
        for (int e = 0; e < NEXP; e++)
            if (e != i0 && lg[e] > lg[i1]) i1 = e;

        float ev  = expf(lg[i1] - lg[i0]);     // <= 1
        float inv = 1.f / (1.f + ev);
        float p0  = inv;
        float p1  = ev * inv;

        int pos0 = atomicAdd(&g_cnt[i0], 1);
        g_tok[i0 * T_TOK + pos0]   = t * 2;
        g_score[i0 * T_TOK + pos0] = p0;
        int pos1 = atomicAdd(&g_cnt[i1], 1);
        g_tok[i1 * T_TOK + pos1]   = t * 2 + 1;
        g_score[i1 * T_TOK + pos1] = p1;
    }
}

// ---------------------------------------------------------------------------
// GEMM1: for expert e, h[e*T + pos, :] = relu( x[tok(pos), :] @ W1[e] + b1[e] )
// Tile 128x128, BK=16, 256 threads, 8x8 micro-tile.
__global__ __launch_bounds__(256, 2)
void gemm1_kernel(const float* __restrict__ x,
                  const float* __restrict__ W1,
                  const float* __restrict__ b1) {
    const int e   = blockIdx.z;
    const int cnt = g_cnt[e];
    const int m0  = blockIdx.y * 128;
    if (m0 >= cnt) return;
    const int n0  = blockIdx.x * 128;

    __shared__ float  As[16][128];
    __shared__ float4 Bs[16][32];

    const int tid = threadIdx.x;
    const int tx  = tid & 15;
    const int ty  = tid >> 4;

    // A loading assignment: 512 float4 per K-tile, 2 per thread
    const int arow = tid >> 2;   // 0..63, second is +64
    const int akq  = tid & 3;    // float4 index along K within tile
    int tokA[2];
#pragma unroll
    for (int p = 0; p < 2; p++) {
        int pos = m0 + arow + p * 64;
        int tk  = 0;
        if (pos < cnt) tk = g_tok[e * T_TOK + pos] >> 1;   // token id
        tokA[p] = tk;
    }
    const float4* x4 = reinterpret_cast<const float4*>(x);

    // B loading assignment
    const int bn4 = tid & 31;
    const int bk  = tid >> 5;    // 0..7, +8 for p=1
    const float4* W4 = reinterpret_cast<const float4*>(W1);
    const size_t  wbase = (size_t)e * DIM * (HID / 4);

    float acc[8][8];
#pragma unroll
    for (int i = 0; i < 8; i++)
#pragma unroll
        for (int j = 0; j < 8; j++) acc[i][j] = 0.f;

    for (int k0 = 0; k0 < DIM; k0 += 16) {
#pragma unroll
        for (int p = 0; p < 2; p++) {
            float4 v = x4[(size_t)tokA[p] * (DIM / 4) + (k0 >> 2) + akq];
            int r = arow + p * 64;
            As[akq * 4 + 0][r] = v.x;
            As[akq * 4 + 1][r] = v.y;
            As[akq * 4 + 2][r] = v.z;
            As[akq * 4 + 3][r] = v.w;
        }
#pragma unroll
        for (int p = 0; p < 2; p++) {
            int k = k0 + bk + p * 8;
            Bs[bk + p * 8][bn4] = W4[wbase + (size_t)k * (HID / 4) + (n0 >> 2) + bn4];
        }
        __syncthreads();

#pragma unroll
        for (int kk = 0; kk < 16; kk++) {
            const float4* Ar = reinterpret_cast<const float4*>(&As[kk][0]);
            float4 a0 = Ar[ty * 2];
            float4 a1 = Ar[ty * 2 + 1];
            float4 b0 = Bs[kk][tx * 2];
            float4 b1v = Bs[kk][tx * 2 + 1];
            float av[8] = {a0.x, a0.y, a0.z, a0.w, a1.x, a1.y, a1.z, a1.w};
            float bv[8] = {b0.x, b0.y, b0.z, b0.w, b1v.x, b1v.y, b1v.z, b1v.w};
#pragma unroll
            for (int i = 0; i < 8; i++)
#pragma unroll
                for (int j = 0; j < 8; j++)
                    acc[i][j] = fmaf(av[i], bv[j], acc[i][j]);
        }
        __syncthreads();
    }

    // epilogue: + b1, relu, store to g_h
    const float4* b14 = reinterpret_cast<const float4*>(b1);
    float4 bb0 = b14[(e * HID + n0) / 4 + tx * 2];
    float4 bb1 = b14[(e * HID + n0) / 4 + tx * 2 + 1];
    float4* h4 = reinterpret_cast<float4*>(g_h);
#pragma unroll
    for (int i = 0; i < 8; i++) {
        int pos = m0 + ty * 8 + i;
        if (pos < cnt) {
            size_t base = ((size_t)e * T_TOK + pos) * (HID / 4) + (n0 >> 2) + tx * 2;
            float4 o0, o1;
            o0.x = fmaxf(acc[i][0] + bb0.x, 0.f);
            o0.y = fmaxf(acc[i][1] + bb0.y, 0.f);
            o0.z = fmaxf(acc[i][2] + bb0.z, 0.f);
            o0.w = fmaxf(acc[i][3] + bb0.w, 0.f);
            o1.x = fmaxf(acc[i][4] + bb1.x, 0.f);
            o1.y = fmaxf(acc[i][5] + bb1.y, 0.f);
            o1.z = fmaxf(acc[i][6] + bb1.z, 0.f);
            o1.w = fmaxf(acc[i][7] + bb1.w, 0.f);
            h4[base]     = o0;
            h4[base + 1] = o1;
        }
    }
}

// ---------------------------------------------------------------------------
// GEMM2: eo[tok2, :] = score * ( h[e*T+pos, :] @ W2[e] + b2[e] )
__global__ __launch_bounds__(256, 2)
void gemm2_kernel(const float* __restrict__ W2,
                  const float* __restrict__ b2) {
    const int e   = blockIdx.z;
    const int cnt = g_cnt[e];
    const int m0  = blockIdx.y * 128;
    if (m0 >= cnt) return;
    const int n0  = blockIdx.x * 128;   // over DIM

    __shared__ float  As[16][128];
    __shared__ float4 Bs[16][32];

    const int tid = threadIdx.x;
    const int tx  = tid & 15;
    const int ty  = tid >> 4;

    const int arow = tid >> 2;
    const int akq  = tid & 3;
    const int bn4  = tid & 31;
    const int bk   = tid >> 5;

    const float4* h4  = reinterpret_cast<const float4*>(g_h);
    const float4* W4  = reinterpret_cast<const float4*>(W2);
    const size_t  abase = ((size_t)e * T_TOK + m0) * (HID / 4);
    const size_t  wbase = (size_t)e * HID * (DIM / 4);

    float acc[8][8];
#pragma unroll
    for (int i = 0; i < 8; i++)
#pragma unroll
        for (int j = 0; j < 8; j++) acc[i][j] = 0.f;

    for (int k0 = 0; k0 < HID; k0 += 16) {
#pragma unroll
        for (int p = 0; p < 2; p++) {
            int r = arow + p * 64;
            // rows >= cnt read stale-but-finite scratch; stores are masked below
            float4 v = h4[abase + (size_t)r * (HID / 4) + (k0 >> 2) + akq];
            As[akq * 4 + 0][r] = v.x;
            As[akq * 4 + 1][r] = v.y;
            As[akq * 4 + 2][r] = v.z;
            As[akq * 4 + 3][r] = v.w;
        }
#pragma unroll
        for (int p = 0; p < 2; p++) {
            int k = k0 + bk + p * 8;
            Bs[bk + p * 8][bn4] = W4[wbase + (size_t)k * (DIM / 4) + (n0 >> 2) + bn4];
        }
        __syncthreads();

#pragma unroll
        for (int kk = 0; kk < 16; kk++) {
            const float4* Ar = reinterpret_cast<const float4*>(&As[kk][0]);
            float4 a0 = Ar[ty * 2];
            float4 a1 = Ar[ty * 2 + 1];
            float4 b0 = Bs[kk][tx * 2];
            float4 b1v = Bs[kk][tx * 2 + 1];
            float av[8] = {a0.x, a0.y, a0.z, a0.w, a1.x, a1.y, a1.z, a1.w};
            float bv[8] = {b0.x, b0.y, b0.z, b0.w, b1v.x, b1v.y, b1v.z, b1v.w};
#pragma unroll
            for (int i = 0; i < 8; i++)
#pragma unroll
                for (int j = 0; j < 8; j++)
                    acc[i][j] = fmaf(av[i], bv[j], acc[i][j]);
        }
        __syncthreads();
    }

    const float4* b24 = reinterpret_cast<const float4*>(b2);
    float4 bb0 = b24[(e * DIM + n0) / 4 + tx * 2];
    float4 bb1 = b24[(e * DIM + n0) / 4 + tx * 2 + 1];
    float4* eo4 = reinterpret_cast<float4*>(g_eo);
#pragma unroll
    for (int i = 0; i < 8; i++) {
        int pos = m0 + ty * 8 + i;
        if (pos < cnt) {
            int   entry = g_tok[e * T_TOK + pos];      // token*2 + slot
            float sc    = g_score[e * T_TOK + pos];
            size_t base = (size_t)entry * (DIM / 4) + (n0 >> 2) + tx * 2;
            float4 o0, o1;
            o0.x = (acc[i][0] + bb0.x) * sc;
            o0.y = (acc[i][1] + bb0.y) * sc;
            o0.z = (acc[i][2] + bb0.z) * sc;
            o0.w = (acc[i][3] + bb0.w) * sc;
            o1.x = (acc[i][4] + bb1.x) * sc;
            o1.y = (acc[i][5] + bb1.y) * sc;
            o1.z = (acc[i][6] + bb1.z) * sc;
            o1.w = (acc[i][7] + bb1.w) * sc;
            eo4[base]     = o0;
            eo4[base + 1] = o1;
        }
    }
}

// ---------------------------------------------------------------------------
// out[t, :] = eo[2t, :] + eo[2t+1, :]
__global__ void combine_kernel(float* __restrict__ out) {
    int i  = blockIdx.x * 256 + threadIdx.x;  // over T*D/4
    int t  = i >> 8;                          // D/4 = 256 float4 per row
    int d4 = i & 255;
    const float4* eo4 = reinterpret_cast<const float4*>(g_eo);
    float4 u = eo4[(size_t)(t * 2) * (DIM / 4) + d4];
    float4 v = eo4[(size_t)(t * 2 + 1) * (DIM / 4) + d4];
    float4 r;
    r.x = u.x + v.x; r.y = u.y + v.y; r.z = u.z + v.z; r.w = u.w + v.w;
    reinterpret_cast<float4*>(out)[i] = r;
}

// ---------------------------------------------------------------------------
extern "C" void kernel_launch(void* const* d_in, const int* in_sizes, int n_in,
                              void* d_out, int out_size) {
    (void)in_sizes; (void)n_in; (void)out_size;
    const float* x  = (const float*)d_in[0];
    const float* Wr = (const float*)d_in[1];
    const float* br = (const float*)d_in[2];
    const float* W1 = (const float*)d_in[3];
    const float* b1 = (const float*)d_in[4];
    const float* W2 = (const float*)d_in[5];
    const float* b2 = (const float*)d_in[6];
    // d_in[7] is k (==2), hardcoded

    zero_cnt_kernel<<<1, 32>>>();
    router_kernel<<<T_TOK, 128>>>(x, Wr, br);

    dim3 g1(HID / 128, T_TOK / 128, NEXP);   // early-exit past per-expert count
    gemm1_kernel<<<g1, 256>>>(x, W1, b1);

    dim3 g2(DIM / 128, T_TOK / 128, NEXP);
    gemm2_kernel<<<g2, 256>>>(W2, b2);

    combine_kernel<<<(T_TOK * DIM / 4) / 256, 256>>>((float*)d_out);
}